// round 2
// baseline (speedup 1.0000x reference)
#include <cuda_runtime.h>
#include <cfloat>

#define DDIM 256
#define BM   64
#define BK   64
#define MAXK 2048
#define MAXN (1 << 17)

__device__ float  g_cn[MAXK];    // fp32 codebook norms (fp64-accumulated)
__device__ float  g_zn[MAXN];    // fp32 row norms     (fp64-accumulated)
__device__ int    g_idx[MAXN];
__device__ double g_loss_acc;

// ---------------------------------------------------------------------------
// K1: norms in fp64, rounded to fp32. One block per row (z rows then codes).
// ---------------------------------------------------------------------------
__global__ void k_norms(const float* __restrict__ z,
                        const float* __restrict__ emb, int N) {
    const int b = blockIdx.x;
    const int t = threadIdx.x;
    const float* src = (b < N) ? (z + (size_t)b * DDIM)
                               : (emb + (size_t)(b - N) * DDIM);
    const float x = src[t];
    double v = (double)x * (double)x;
    __shared__ double s[8];
    #pragma unroll
    for (int o = 16; o; o >>= 1) v += __shfl_down_sync(0xFFFFFFFFu, v, o);
    if ((t & 31) == 0) s[t >> 5] = v;
    __syncthreads();
    if (t == 0) {
        double sum = 0.0;
        #pragma unroll
        for (int i = 0; i < 8; i++) sum += s[i];
        if (b < N) g_zn[b] = (float)sum; else g_cn[b - N] = (float)sum;
        if (b == 0) g_loss_acc = 0.0;
    }
}

// ---------------------------------------------------------------------------
// K2: fused GEMM (fp64 accumulate) + reference-faithful fp32 quantized argmin
//     dist_k = fl( fl(zn32 + cn32_k) - 2 * fl32(dot64_k) ), first-min wins.
// ---------------------------------------------------------------------------
__device__ __forceinline__ int sw_addr(int d, int r) {
    return d * 64 + 4 * ((r >> 2) ^ (d & 15)) + (r & 3);
}

__global__ void __launch_bounds__(256, 1)
k_argmax(const float4* __restrict__ z, const float4* __restrict__ emb,
         float* __restrict__ out_idx_f, int K) {
    extern __shared__ float sm[];
    float* zt = sm;                          // 256*64 floats
    float* et = sm + DDIM * BM;              // 256*64 floats
    unsigned long long* keys =
        (unsigned long long*)(sm + 2 * DDIM * BM);

    const int tid = threadIdx.x;
    const int tx = tid & 15;
    const int ty = tid >> 4;
    const int row0 = blockIdx.x * BM;

    if (tid < BM) keys[tid] = 0xFFFFFFFFFFFFFFFFull;

    for (int i = tid; i < BM * (DDIM / 4); i += 256) {
        const int r  = i >> 6;
        const int dv = i & 63;
        float4 v = z[(size_t)(row0 + r) * (DDIM / 4) + dv];
        const int d = dv * 4;
        float vv[4] = {v.x, v.y, v.z, v.w};
        #pragma unroll
        for (int q = 0; q < 4; q++) zt[sw_addr(d + q, r)] = vv[q];
    }

    float znr[4];
    #pragma unroll
    for (int i = 0; i < 4; i++) znr[i] = g_zn[row0 + ty * 4 + i];

    float bestS[4];
    int   bestI[4];
    #pragma unroll
    for (int i = 0; i < 4; i++) { bestS[i] = FLT_MAX; bestI[i] = 0; }

    const float4* zt4 = (const float4*)zt;
    const float4* et4 = (const float4*)et;

    for (int kt = 0; kt < K; kt += BK) {
        __syncthreads();
        for (int i = tid; i < BK * (DDIM / 4); i += 256) {
            const int r  = i >> 6;
            const int dv = i & 63;
            float4 v = emb[(size_t)(kt + r) * (DDIM / 4) + dv];
            const int d = dv * 4;
            float vv[4] = {v.x, v.y, v.z, v.w};
            #pragma unroll
            for (int q = 0; q < 4; q++) et[sw_addr(d + q, r)] = vv[q];
        }
        __syncthreads();

        double acc[4][4];
        #pragma unroll
        for (int i = 0; i < 4; i++)
            #pragma unroll
            for (int j = 0; j < 4; j++) acc[i][j] = 0.0;

        #pragma unroll 4
        for (int d = 0; d < DDIM; d++) {
            const int s = d & 15;
            const float4 zv = zt4[d * 16 + (ty ^ s)];
            const float4 ev = et4[d * 16 + (tx ^ s)];
            const double zx = zv.x, zy = zv.y, zz = zv.z, zw = zv.w;
            const double ex = ev.x, ey = ev.y, ez = ev.z, ew = ev.w;
            acc[0][0] += zx * ex;  acc[0][1] += zx * ey;
            acc[0][2] += zx * ez;  acc[0][3] += zx * ew;
            acc[1][0] += zy * ex;  acc[1][1] += zy * ey;
            acc[1][2] += zy * ez;  acc[1][3] += zy * ew;
            acc[2][0] += zz * ex;  acc[2][1] += zz * ey;
            acc[2][2] += zz * ez;  acc[2][3] += zz * ew;
            acc[3][0] += zw * ex;  acc[3][1] += zw * ey;
            acc[3][2] += zw * ez;  acc[3][3] += zw * ew;
        }

        // reference-faithful scoring (ascending k; strict < keeps lowest idx)
        #pragma unroll
        for (int j = 0; j < 4; j++) {
            const int k = kt + tx * 4 + j;
            const float cn = g_cn[k];
            #pragma unroll
            for (int i = 0; i < 4; i++) {
                const float zc   = znr[i] + cn;           // fl(zn + cn)
                const float dotf = (float)acc[i][j];      // fl32(dot)
                const float s    = zc - 2.0f * dotf;      // fl(zc - 2*dot)
                if (s < bestS[i]) { bestS[i] = s; bestI[i] = k; }
            }
        }
    }
    __syncthreads();

    // cross-thread argmin: ascending u64 key = mono(dist) << 32 | idx
    #pragma unroll
    for (int i = 0; i < 4; i++) {
        unsigned u = __float_as_uint(bestS[i]);
        u = (u & 0x80000000u) ? ~u : (u | 0x80000000u);
        unsigned long long key =
            ((unsigned long long)u << 32) | (unsigned)bestI[i];
        atomicMin(&keys[ty * 4 + i], key);
    }
    __syncthreads();

    if (tid < BM) {
        const int idx = (int)(unsigned)(keys[tid] & 0xFFFFFFFFull);
        const int r = row0 + tid;
        g_idx[r] = idx;
        out_idx_f[r] = (float)idx;
    }
}

// ---------------------------------------------------------------------------
// K3: gather + straight-through output fl(z + fl(q - z)) + loss accumulation
// ---------------------------------------------------------------------------
__global__ void k_gather(const float4* __restrict__ z,
                         const float4* __restrict__ emb,
                         float4* __restrict__ outq, int total4) {
    double lsum = 0.0;
    const int stride = gridDim.x * blockDim.x;
    for (int e = blockIdx.x * blockDim.x + threadIdx.x; e < total4; e += stride) {
        const int row = e >> 6;
        const int t   = e & 63;
        const int idx = g_idx[row];
        const float4 ev = emb[(size_t)idx * 64 + t];
        const float4 zv = z[e];
        const float dx = ev.x - zv.x, dy = ev.y - zv.y;
        const float dz = ev.z - zv.z, dw = ev.w - zv.w;
        float4 o;                              // straight-through: z + (q - z)
        o.x = zv.x + dx; o.y = zv.y + dy; o.z = zv.z + dz; o.w = zv.w + dw;
        outq[e] = o;
        const float sx = dx * dx, sy = dy * dy, sz = dz * dz, sw = dw * dw;
        lsum += (double)sx + (double)sy + (double)sz + (double)sw;
    }
    __shared__ double s[8];
    #pragma unroll
    for (int o = 16; o; o >>= 1) lsum += __shfl_down_sync(0xFFFFFFFFu, lsum, o);
    if ((threadIdx.x & 31) == 0) s[threadIdx.x >> 5] = lsum;
    __syncthreads();
    if (threadIdx.x == 0) {
        double b = 0.0;
        #pragma unroll
        for (int i = 0; i < 8; i++) b += s[i];
        atomicAdd(&g_loss_acc, b);
    }
}

__global__ void k_final(float* __restrict__ out_loss, double inv_cnt) {
    *out_loss = (float)(0.25 * g_loss_acc * inv_cnt);
}

// ---------------------------------------------------------------------------
extern "C" void kernel_launch(void* const* d_in, const int* in_sizes, int n_in,
                              void* d_out, int out_size) {
    const float* z   = (const float*)d_in[0];
    const float* emb = (const float*)d_in[1];
    const int N = in_sizes[0] / DDIM;
    const int K = in_sizes[1] / DDIM;

    float* out      = (float*)d_out;
    float* out_q    = out;
    float* out_idx  = out + (size_t)N * DDIM;
    float* out_loss = out_idx + N;

    k_norms<<<N + K, 256>>>(z, emb, N);

    const size_t smem = (size_t)2 * DDIM * BM * sizeof(float)
                      + BM * sizeof(unsigned long long);
    cudaFuncSetAttribute(k_argmax, cudaFuncAttributeMaxDynamicSharedMemorySize,
                         (int)smem);
    k_argmax<<<N / BM, 256, smem>>>((const float4*)z, (const float4*)emb,
                                    out_idx, K);

    k_gather<<<1024, 256>>>((const float4*)z, (const float4*)emb,
                            (float4*)out_q, N * (DDIM / 4));

    k_final<<<1, 1>>>(out_loss, 1.0 / ((double)N * (double)DDIM));
}

// round 3
// speedup vs baseline: 23.7049x; 23.7049x over previous
#include <cuda_runtime.h>
#include <cfloat>

#define DDIM 256
#define TM   128        // rows per CTA tile
#define TN   64         // codes per k-tile
#define MAXK 2048
#define MAXN (1 << 17)

__device__ float  g_cn[MAXK];
__device__ float  g_zn[MAXN];
__device__ int    g_idx[MAXN];
__device__ unsigned long long g_top3[MAXN * 3];
__device__ int    g_flag_cnt;
__device__ int    g_flagged[MAXN];
__device__ double g_loss_acc;

// monotone packing: ascending u64 order == (score asc, idx asc)
__device__ __forceinline__ unsigned long long packkey(float s, int idx) {
    unsigned u = __float_as_uint(s);
    u = (u & 0x80000000u) ? ~u : (u | 0x80000000u);
    return ((unsigned long long)u << 32) | (unsigned)idx;
}
__device__ __forceinline__ float unpackval(unsigned long long k) {
    unsigned u = (unsigned)(k >> 32);
    u = (u & 0x80000000u) ? (u ^ 0x80000000u) : ~u;
    return __uint_as_float(u);
}

// ---------------------------------------------------------------------------
// K1: fp64-accurate norms rounded to fp32; reset accumulators.
// ---------------------------------------------------------------------------
__global__ void k_norms(const float* __restrict__ z,
                        const float* __restrict__ emb, int N) {
    const int b = blockIdx.x;
    const int t = threadIdx.x;
    const float* src = (b < N) ? (z + (size_t)b * DDIM)
                               : (emb + (size_t)(b - N) * DDIM);
    const float x = src[t];
    double v = (double)x * (double)x;
    __shared__ double s[8];
    #pragma unroll
    for (int o = 16; o; o >>= 1) v += __shfl_down_sync(0xFFFFFFFFu, v, o);
    if ((t & 31) == 0) s[t >> 5] = v;
    __syncthreads();
    if (t == 0) {
        double sum = 0.0;
        #pragma unroll
        for (int i = 0; i < 8; i++) sum += s[i];
        if (b < N) g_zn[b] = (float)sum; else g_cn[b - N] = (float)sum;
        if (b == 0) { g_loss_acc = 0.0; g_flag_cnt = 0; }
    }
}

// ---------------------------------------------------------------------------
// K2: fp32 GEMM + per-row approx top-3 (quantized reference scoring).
// Tiles transposed [D][rows] with XOR-group swizzle; thread = 8 rows x 4 codes.
// ---------------------------------------------------------------------------
__global__ void __launch_bounds__(256, 1)
k_gemm(const float4* __restrict__ z, const float4* __restrict__ emb, int K) {
    extern __shared__ float sm[];
    float* zt = sm;                              // 256*128 floats (128KB)
    float* et = sm + DDIM * TM;                  // 256*64  floats (64KB)
    unsigned long long* slots =
        (unsigned long long*)(sm + DDIM * TM + DDIM * TN);   // 128*3 keys

    const int tid = threadIdx.x;
    const int tx = tid & 15;       // code group (4 codes)
    const int ty = tid >> 4;       // row group (8 rows)
    const int row0 = blockIdx.x * TM;

    for (int i = tid; i < TM * 3; i += 256) slots[i] = ~0ull;

    // fill z tile (transposed + swizzled); coalesced float4 global reads
    for (int i = tid; i < TM * (DDIM / 4); i += 256) {
        const int r  = i >> 6;
        const int dv = i & 63;
        float4 v = z[(size_t)(row0 + r) * (DDIM / 4) + dv];
        const int d = dv * 4;
        float vv[4] = {v.x, v.y, v.z, v.w};
        #pragma unroll
        for (int q = 0; q < 4; q++)
            zt[(d + q) * TM + 4 * ((r >> 2) ^ ((d + q) & 31)) + (r & 3)] = vv[q];
    }

    float znr[8];
    #pragma unroll
    for (int i = 0; i < 8; i++) znr[i] = g_zn[row0 + ty * 8 + i];

    unsigned long long b1[8], b2[8], b3[8];
    #pragma unroll
    for (int i = 0; i < 8; i++) { b1[i] = ~0ull; b2[i] = ~0ull; b3[i] = ~0ull; }

    const float4* zt4 = (const float4*)zt;
    const float4* et4 = (const float4*)et;

    for (int kt = 0; kt < K; kt += TN) {
        __syncthreads();
        for (int i = tid; i < TN * (DDIM / 4); i += 256) {
            const int r  = i >> 6;
            const int dv = i & 63;
            float4 v = emb[(size_t)(kt + r) * (DDIM / 4) + dv];
            const int d = dv * 4;
            float vv[4] = {v.x, v.y, v.z, v.w};
            #pragma unroll
            for (int q = 0; q < 4; q++)
                et[(d + q) * TN + 4 * ((r >> 2) ^ ((d + q) & 15)) + (r & 3)] = vv[q];
        }
        __syncthreads();

        float acc[8][4];
        #pragma unroll
        for (int i = 0; i < 8; i++)
            #pragma unroll
            for (int j = 0; j < 4; j++) acc[i][j] = 0.f;

        #pragma unroll 8
        for (int d = 0; d < DDIM; d++) {
            const int s5 = d & 31, s4 = d & 15;
            const float4 za = zt4[d * 32 + ((ty * 2)     ^ s5)];
            const float4 zb = zt4[d * 32 + ((ty * 2 + 1) ^ s5)];
            const float4 ev = et4[d * 16 + (tx ^ s4)];
            const float e[4] = {ev.x, ev.y, ev.z, ev.w};
            const float a[8] = {za.x, za.y, za.z, za.w, zb.x, zb.y, zb.z, zb.w};
            #pragma unroll
            for (int i = 0; i < 8; i++)
                #pragma unroll
                for (int j = 0; j < 4; j++) acc[i][j] += a[i] * e[j];
        }

        #pragma unroll
        for (int j = 0; j < 4; j++) {
            const int k = kt + tx * 4 + j;
            const float cn = g_cn[k];
            #pragma unroll
            for (int i = 0; i < 8; i++) {
                const float s = (znr[i] + cn) - 2.0f * acc[i][j];
                const unsigned long long key = packkey(s, k);
                if (key < b3[i]) {
                    if (key < b2[i]) {
                        b3[i] = b2[i];
                        if (key < b1[i]) { b2[i] = b1[i]; b1[i] = key; }
                        else             { b2[i] = key; }
                    } else b3[i] = key;
                }
            }
        }
    }

    // 3-round cross-thread top-3 merge
    __syncthreads();
    #pragma unroll
    for (int i = 0; i < 8; i++)
        atomicMin(&slots[(ty * 8 + i) * 3 + 0], b1[i]);
    __syncthreads();
    #pragma unroll
    for (int i = 0; i < 8; i++) {
        const int r = ty * 8 + i;
        const unsigned long long w1 = slots[r * 3 + 0];
        atomicMin(&slots[r * 3 + 1], (b1[i] == w1) ? b2[i] : b1[i]);
    }
    __syncthreads();
    #pragma unroll
    for (int i = 0; i < 8; i++) {
        const int r = ty * 8 + i;
        const unsigned long long w1 = slots[r * 3 + 0];
        const unsigned long long w2 = slots[r * 3 + 1];
        unsigned long long c = b1[i];
        if (c == w1 || c == w2) c = b2[i];
        if (c == w1 || c == w2) c = b3[i];
        atomicMin(&slots[r * 3 + 2], c);
    }
    __syncthreads();

    if (tid < TM) {
        const int r = row0 + tid;
        g_top3[(size_t)r * 3 + 0] = slots[tid * 3 + 0];
        g_top3[(size_t)r * 3 + 1] = slots[tid * 3 + 1];
        g_top3[(size_t)r * 3 + 2] = slots[tid * 3 + 2];
    }
}

// ---------------------------------------------------------------------------
// K3: exact fp64 rescore of per-row top-2; flag unsafe rows. Warp per row.
// ---------------------------------------------------------------------------
__global__ void k_resolve(const float* __restrict__ z,
                          const float* __restrict__ emb,
                          float* __restrict__ out_idx_f) {
    const int row  = blockIdx.x * 8 + (threadIdx.x >> 5);
    const int lane = threadIdx.x & 31;

    const unsigned long long w1 = g_top3[(size_t)row * 3 + 0];
    const unsigned long long w2 = g_top3[(size_t)row * 3 + 1];
    const unsigned long long w3 = g_top3[(size_t)row * 3 + 2];
    const int i1 = (int)(unsigned)(w1 & 0xFFFFFFFFull);
    const int i2 = (int)(unsigned)(w2 & 0xFFFFFFFFull);

    double d1 = 0.0, d2 = 0.0;
    const float* zr = z + (size_t)row * DDIM;
    const float* e1 = emb + (size_t)i1 * DDIM;
    const float* e2 = emb + (size_t)i2 * DDIM;
    #pragma unroll
    for (int t = 0; t < DDIM / 32; t++) {
        const int d = lane + t * 32;
        const double zd = (double)zr[d];
        d1 += zd * (double)e1[d];
        d2 += zd * (double)e2[d];
    }
    #pragma unroll
    for (int o = 16; o; o >>= 1) {
        d1 += __shfl_down_sync(0xFFFFFFFFu, d1, o);
        d2 += __shfl_down_sync(0xFFFFFFFFu, d2, o);
    }

    if (lane == 0) {
        const float zn = g_zn[row];
        const float s1e = (zn + g_cn[i1]) - 2.0f * (float)d1;
        const float s2e = (zn + g_cn[i2]) - 2.0f * (float)d2;
        int win = i1;
        if (s2e < s1e || (s2e == s1e && i2 < i1)) win = i2;
        g_idx[row] = win;
        out_idx_f[row] = (float)win;
        // safety: exact winner provably in {i1,i2} unless 3rd approx score
        // is within band of the approx min
        const float s1a = unpackval(w1);
        const float s3a = unpackval(w3);
        if (!(s3a > s1a + 2e-4f)) {
            const int p = atomicAdd(&g_flag_cnt, 1);
            g_flagged[p] = row;
        }
    }
}

// ---------------------------------------------------------------------------
// K4: full-K fp64 fallback for flagged rows (rare).
// ---------------------------------------------------------------------------
__global__ void k_fallback(const float* __restrict__ z,
                           const float* __restrict__ emb,
                           float* __restrict__ out_idx_f, int K) {
    __shared__ float zrow[DDIM];
    __shared__ unsigned long long best;
    const int cnt = g_flag_cnt;
    for (int f = blockIdx.x; f < cnt; f += gridDim.x) {
        const int row = g_flagged[f];
        if (threadIdx.x == 0) best = ~0ull;
        for (int t = threadIdx.x; t < DDIM; t += blockDim.x)
            zrow[t] = z[(size_t)row * DDIM + t];
        __syncthreads();
        const float zn = g_zn[row];
        unsigned long long lb = ~0ull;
        for (int k = threadIdx.x; k < K; k += blockDim.x) {
            double dot = 0.0;
            const float* ek = emb + (size_t)k * DDIM;
            #pragma unroll 8
            for (int d = 0; d < DDIM; d++)
                dot += (double)zrow[d] * (double)ek[d];
            const float s = (zn + g_cn[k]) - 2.0f * (float)dot;
            const unsigned long long key = packkey(s, k);
            if (key < lb) lb = key;
        }
        atomicMin(&best, lb);
        __syncthreads();
        if (threadIdx.x == 0) {
            const int win = (int)(unsigned)(best & 0xFFFFFFFFull);
            g_idx[row] = win;
            out_idx_f[row] = (float)win;
        }
        __syncthreads();
    }
}

// ---------------------------------------------------------------------------
// K5: gather + straight-through fl(z + fl(q - z)) + fp64 loss accumulation
// ---------------------------------------------------------------------------
__global__ void k_gather(const float4* __restrict__ z,
                         const float4* __restrict__ emb,
                         float4* __restrict__ outq, int total4) {
    double lsum = 0.0;
    const int stride = gridDim.x * blockDim.x;
    for (int e = blockIdx.x * blockDim.x + threadIdx.x; e < total4; e += stride) {
        const int row = e >> 6;
        const int t   = e & 63;
        const int idx = g_idx[row];
        const float4 ev = emb[(size_t)idx * 64 + t];
        const float4 zv = z[e];
        const float dx = ev.x - zv.x, dy = ev.y - zv.y;
        const float dz = ev.z - zv.z, dw = ev.w - zv.w;
        float4 o;
        o.x = zv.x + dx; o.y = zv.y + dy; o.z = zv.z + dz; o.w = zv.w + dw;
        outq[e] = o;
        lsum += (double)(dx * dx) + (double)(dy * dy)
              + (double)(dz * dz) + (double)(dw * dw);
    }
    __shared__ double s[8];
    #pragma unroll
    for (int o = 16; o; o >>= 1) lsum += __shfl_down_sync(0xFFFFFFFFu, lsum, o);
    if ((threadIdx.x & 31) == 0) s[threadIdx.x >> 5] = lsum;
    __syncthreads();
    if (threadIdx.x == 0) {
        double b = 0.0;
        #pragma unroll
        for (int i = 0; i < 8; i++) b += s[i];
        atomicAdd(&g_loss_acc, b);
    }
}

__global__ void k_final(float* __restrict__ out_loss, double inv_cnt) {
    *out_loss = (float)(0.25 * g_loss_acc * inv_cnt);
}

// ---------------------------------------------------------------------------
extern "C" void kernel_launch(void* const* d_in, const int* in_sizes, int n_in,
                              void* d_out, int out_size) {
    const float* z   = (const float*)d_in[0];
    const float* emb = (const float*)d_in[1];
    const int N = in_sizes[0] / DDIM;
    const int K = in_sizes[1] / DDIM;

    float* out      = (float*)d_out;
    float* out_q    = out;
    float* out_idx  = out + (size_t)N * DDIM;
    float* out_loss = out_idx + N;

    k_norms<<<N + K, 256>>>(z, emb, N);

    const size_t smem = (size_t)(DDIM * TM + DDIM * TN) * sizeof(float)
                      + TM * 3 * sizeof(unsigned long long);
    cudaFuncSetAttribute(k_gemm, cudaFuncAttributeMaxDynamicSharedMemorySize,
                         (int)smem);
    k_gemm<<<N / TM, 256, smem>>>((const float4*)z, (const float4*)emb, K);

    k_resolve<<<N / 8, 256>>>(z, emb, out_idx);
    k_fallback<<<512, 256>>>(z, emb, out_idx, K);

    k_gather<<<1024, 256>>>((const float4*)z, (const float4*)emb,
                            (float4*)out_q, N * (DDIM / 4));

    k_final<<<1, 1>>>(out_loss, 1.0 / ((double)N * (double)DDIM));
}

// round 4
// speedup vs baseline: 28.1919x; 1.1893x over previous
#include <cuda_runtime.h>
#include <cfloat>
#include <math.h>

#define DDIM 256
#define TM   128        // rows per CTA tile
#define TN   64         // codes per k-tile
#define MAXK 2048
#define MAXN (1 << 17)
#define CAND_CAP 32

__device__ float  g_cn[MAXK];
__device__ float  g_zn[MAXN];
__device__ int    g_idx[MAXN];
__device__ int    g_flag_cnt;
__device__ int    g_flagged[MAXN];
__device__ double g_loss_acc;
__device__ float4 g_S[(size_t)MAXN * 256];   // approx scores, stride 1024 floats

// monotone packing: ascending u64 order == (score asc, idx asc)
__device__ __forceinline__ unsigned long long packkey(float s, int idx) {
    unsigned u = __float_as_uint(s);
    u = (u & 0x80000000u) ? ~u : (u | 0x80000000u);
    return ((unsigned long long)u << 32) | (unsigned)idx;
}
__device__ __forceinline__ float unpackval(unsigned long long k) {
    unsigned u = (unsigned)(k >> 32);
    u = (u & 0x80000000u) ? (u ^ 0x80000000u) : ~u;
    return __uint_as_float(u);
}

// packed f32x2 helpers
__device__ __forceinline__ void ffma2(unsigned long long& acc,
                                      unsigned long long a,
                                      unsigned long long b) {
    asm("fma.rn.f32x2 %0, %1, %2, %0;" : "+l"(acc) : "l"(a), "l"(b));
}
__device__ __forceinline__ unsigned long long splat2(float x) {
    unsigned long long r;
    asm("mov.b64 %0, {%1, %1};" : "=l"(r) : "f"(x));
    return r;
}
__device__ __forceinline__ void unpack2(unsigned long long v,
                                        float& lo, float& hi) {
    asm("mov.b64 {%0, %1}, %2;" : "=f"(lo), "=f"(hi) : "l"(v));
}

// ---------------------------------------------------------------------------
// K1: fp64-accurate norms rounded to fp32; reset accumulators.
// ---------------------------------------------------------------------------
__global__ void k_norms(const float* __restrict__ z,
                        const float* __restrict__ emb, int N) {
    const int b = blockIdx.x;
    const int t = threadIdx.x;
    const float* src = (b < N) ? (z + (size_t)b * DDIM)
                               : (emb + (size_t)(b - N) * DDIM);
    const float x = src[t];
    double v = (double)x * (double)x;
    __shared__ double s[8];
    #pragma unroll
    for (int o = 16; o; o >>= 1) v += __shfl_down_sync(0xFFFFFFFFu, v, o);
    if ((t & 31) == 0) s[t >> 5] = v;
    __syncthreads();
    if (t == 0) {
        double sum = 0.0;
        #pragma unroll
        for (int i = 0; i < 8; i++) sum += s[i];
        if (b < N) g_zn[b] = (float)sum; else g_cn[b - N] = (float)sum;
        if (b == 0) { g_loss_acc = 0.0; g_flag_cnt = 0; }
    }
}

// ---------------------------------------------------------------------------
// K2: fp32 GEMM (packed FFMA2) computing quantized approx scores -> g_S.
// Transposed swizzled tiles; thread = 8 rows (4 packed pairs) x 4 codes.
// ---------------------------------------------------------------------------
__global__ void __launch_bounds__(256, 1)
k_gemm(const float4* __restrict__ z, const float4* __restrict__ emb, int K) {
    extern __shared__ float sm[];
    float* zt = sm;                          // 256*128 floats (128KB)
    float* et = sm + DDIM * TM;              // 256*64  floats (64KB)

    const int tid = threadIdx.x;
    const int tx = tid & 15;       // code group (4 codes)
    const int ty = tid >> 4;       // row group (8 rows = 4 pairs)
    const int row0 = blockIdx.x * TM;

    // fill z tile (transposed + swizzled); coalesced float4 global reads
    for (int i = tid; i < TM * (DDIM / 4); i += 256) {
        const int r  = i >> 6;
        const int dv = i & 63;
        float4 v = z[(size_t)(row0 + r) * (DDIM / 4) + dv];
        const int d = dv * 4;
        float vv[4] = {v.x, v.y, v.z, v.w};
        #pragma unroll
        for (int q = 0; q < 4; q++)
            zt[(d + q) * TM + 4 * ((r >> 2) ^ ((d + q) & 31)) + (r & 3)] = vv[q];
    }

    float znr[8];
    #pragma unroll
    for (int i = 0; i < 8; i++) znr[i] = g_zn[row0 + ty * 8 + i];

    const ulonglong2* ztU = (const ulonglong2*)zt;
    const float4*     et4 = (const float4*)et;
    const float4*     cn4 = (const float4*)g_cn;

    for (int kt = 0; kt < K; kt += TN) {
        __syncthreads();
        for (int i = tid; i < TN * (DDIM / 4); i += 256) {
            const int r  = i >> 6;
            const int dv = i & 63;
            float4 v = emb[(size_t)(kt + r) * (DDIM / 4) + dv];
            const int d = dv * 4;
            float vv[4] = {v.x, v.y, v.z, v.w};
            #pragma unroll
            for (int q = 0; q < 4; q++)
                et[(d + q) * TN + 4 * ((r >> 2) ^ ((d + q) & 15)) + (r & 3)] = vv[q];
        }
        __syncthreads();

        unsigned long long acc[4][4];   // [row pair][code], packed f32x2
        #pragma unroll
        for (int p = 0; p < 4; p++)
            #pragma unroll
            for (int j = 0; j < 4; j++) acc[p][j] = 0ull;

        #pragma unroll 8
        for (int d = 0; d < DDIM; d++) {
            const int s5 = d & 31, s4 = d & 15;
            const ulonglong2 za = ztU[d * 32 + ((ty * 2)     ^ s5)];
            const ulonglong2 zb = ztU[d * 32 + ((ty * 2 + 1) ^ s5)];
            const float4 ev = et4[d * 16 + (tx ^ s4)];
            unsigned long long es[4];
            es[0] = splat2(ev.x); es[1] = splat2(ev.y);
            es[2] = splat2(ev.z); es[3] = splat2(ev.w);
            const unsigned long long zp[4] = {za.x, za.y, zb.x, zb.y};
            #pragma unroll
            for (int p = 0; p < 4; p++)
                #pragma unroll
                for (int j = 0; j < 4; j++) ffma2(acc[p][j], zp[p], es[j]);
        }

        // quantized scores s = fl( fl(zn+cn) - 2*dot ), store to g_S
        const float4 cnv = cn4[(kt >> 2) + tx];
        const float cns[4] = {cnv.x, cnv.y, cnv.z, cnv.w};
        #pragma unroll
        for (int p = 0; p < 4; p++) {
            float dlo[4], dhi[4];
            #pragma unroll
            for (int j = 0; j < 4; j++) unpack2(acc[p][j], dlo[j], dhi[j]);
            const float zna = znr[2 * p], znb = znr[2 * p + 1];
            float4 sa, sb;
            sa.x = (zna + cns[0]) - 2.0f * dlo[0];
            sa.y = (zna + cns[1]) - 2.0f * dlo[1];
            sa.z = (zna + cns[2]) - 2.0f * dlo[2];
            sa.w = (zna + cns[3]) - 2.0f * dlo[3];
            sb.x = (znb + cns[0]) - 2.0f * dhi[0];
            sb.y = (znb + cns[1]) - 2.0f * dhi[1];
            sb.z = (znb + cns[2]) - 2.0f * dhi[2];
            sb.w = (znb + cns[3]) - 2.0f * dhi[3];
            const int ra = row0 + ty * 8 + 2 * p;
            g_S[(size_t)ra * 256 + (kt >> 2) + tx]       = sa;
            g_S[(size_t)(ra + 1) * 256 + (kt >> 2) + tx] = sb;
        }
    }
}

// ---------------------------------------------------------------------------
// K3: per-row select. Find approx min, collect provable candidate band,
//     rescore candidates with exact fp64 dots. Warp per row.
// ---------------------------------------------------------------------------
__global__ void __launch_bounds__(256)
k_select(const float* __restrict__ z, const float* __restrict__ emb,
         float* __restrict__ out_idx_f, int K) {
    __shared__ int scnt[8];
    __shared__ int scand[8][CAND_CAP];

    const int warp = threadIdx.x >> 5;
    const int lane = threadIdx.x & 31;
    const int row  = blockIdx.x * 8 + warp;
    const float4* srow = g_S + (size_t)row * 256;
    const int E = K / 4;                      // float4 elements per row

    if (lane == 0) scnt[warp] = 0;
    __syncwarp();

    // pass 1: min key
    unsigned long long bk = ~0ull;
    for (int e = lane; e < E; e += 32) {
        const float4 v = srow[e];
        const int k = e * 4;
        unsigned long long k0 = packkey(v.x, k);
        unsigned long long k1 = packkey(v.y, k + 1);
        unsigned long long k2 = packkey(v.z, k + 2);
        unsigned long long k3 = packkey(v.w, k + 3);
        k0 = min(k0, k1); k2 = min(k2, k3); k0 = min(k0, k2);
        bk = min(bk, k0);
    }
    #pragma unroll
    for (int o = 16; o; o >>= 1)
        bk = min(bk, __shfl_xor_sync(0xFFFFFFFFu, bk, o));

    const float smin = unpackval(bk);
    // provable band: 2*(q + 2*eps_dot); q = ulp at smin's binade (+1 safety)
    const float aq = fabsf(smin);
    float qq = (aq > 0.f) ? exp2f((float)(ilogbf(aq) - 22)) : 1e-30f; // 2*ulp
    const float thr = smin + (2.0f * qq + 2e-5f);

    // pass 2: collect candidates
    for (int e = lane; e < E; e += 32) {
        const float4 v = srow[e];
        const float sv[4] = {v.x, v.y, v.z, v.w};
        #pragma unroll
        for (int q = 0; q < 4; q++) {
            if (sv[q] <= thr) {
                const int pos = atomicAdd(&scnt[warp], 1);
                if (pos < CAND_CAP) scand[warp][pos] = e * 4 + q;
            }
        }
    }
    __syncwarp();
    const int cnt = scnt[warp];

    if (cnt > CAND_CAP) {                      // pathological: full fallback
        if (lane == 0) {
            const int p = atomicAdd(&g_flag_cnt, 1);
            g_flagged[p] = row;
        }
        return;
    }

    // exact fp64 rescore of candidates (pairs for ILP)
    float zreg[8];
    const float* zr = z + (size_t)row * DDIM;
    #pragma unroll
    for (int t = 0; t < 8; t++) zreg[t] = zr[lane + 32 * t];
    const float zn = g_zn[row];

    unsigned long long best = ~0ull;
    for (int c = 0; c < cnt; c += 2) {
        const int i1 = scand[warp][c];
        const int i2 = (c + 1 < cnt) ? scand[warp][c + 1] : i1;
        const float* e1 = emb + (size_t)i1 * DDIM;
        const float* e2 = emb + (size_t)i2 * DDIM;
        double d1 = 0.0, d2 = 0.0;
        #pragma unroll
        for (int t = 0; t < 8; t++) {
            const double zd = (double)zreg[t];
            d1 += zd * (double)__ldg(e1 + lane + 32 * t);
            d2 += zd * (double)__ldg(e2 + lane + 32 * t);
        }
        #pragma unroll
        for (int o = 16; o; o >>= 1) {
            d1 += __shfl_down_sync(0xFFFFFFFFu, d1, o);
            d2 += __shfl_down_sync(0xFFFFFFFFu, d2, o);
        }
        if (lane == 0) {
            const float s1 = (zn + g_cn[i1]) - 2.0f * (float)d1;
            best = min(best, packkey(s1, i1));
            if (i2 != i1) {
                const float s2 = (zn + g_cn[i2]) - 2.0f * (float)d2;
                best = min(best, packkey(s2, i2));
            }
        }
    }
    if (lane == 0) {
        const int win = (int)(unsigned)(best & 0xFFFFFFFFull);
        g_idx[row] = win;
        out_idx_f[row] = (float)win;
    }
}

// ---------------------------------------------------------------------------
// K4: full-K fp64 fallback for flagged rows (rare).
// ---------------------------------------------------------------------------
__global__ void k_fallback(const float* __restrict__ z,
                           const float* __restrict__ emb,
                           float* __restrict__ out_idx_f, int K) {
    __shared__ float zrow[DDIM];
    __shared__ unsigned long long best;
    const int cnt = g_flag_cnt;
    for (int f = blockIdx.x; f < cnt; f += gridDim.x) {
        const int row = g_flagged[f];
        if (threadIdx.x == 0) best = ~0ull;
        for (int t = threadIdx.x; t < DDIM; t += blockDim.x)
            zrow[t] = z[(size_t)row * DDIM + t];
        __syncthreads();
        const float zn = g_zn[row];
        unsigned long long lb = ~0ull;
        for (int k = threadIdx.x; k < K; k += blockDim.x) {
            double dot = 0.0;
            const float* ek = emb + (size_t)k * DDIM;
            #pragma unroll 8
            for (int d = 0; d < DDIM; d++)
                dot += (double)zrow[d] * (double)ek[d];
            const float s = (zn + g_cn[k]) - 2.0f * (float)dot;
            lb = min(lb, packkey(s, k));
        }
        atomicMin(&best, lb);
        __syncthreads();
        if (threadIdx.x == 0) {
            const int win = (int)(unsigned)(best & 0xFFFFFFFFull);
            g_idx[row] = win;
            out_idx_f[row] = (float)win;
        }
        __syncthreads();
    }
}

// ---------------------------------------------------------------------------
// K5: gather + straight-through fl(z + fl(q - z)) + fp64 loss accumulation
// ---------------------------------------------------------------------------
__global__ void k_gather(const float4* __restrict__ z,
                         const float4* __restrict__ emb,
                         float4* __restrict__ outq, int total4) {
    double lsum = 0.0;
    const int stride = gridDim.x * blockDim.x;
    for (int e = blockIdx.x * blockDim.x + threadIdx.x; e < total4; e += stride) {
        const int row = e >> 6;
        const int t   = e & 63;
        const int idx = g_idx[row];
        const float4 ev = emb[(size_t)idx * 64 + t];
        const float4 zv = z[e];
        const float dx = ev.x - zv.x, dy = ev.y - zv.y;
        const float dz = ev.z - zv.z, dw = ev.w - zv.w;
        float4 o;
        o.x = zv.x + dx; o.y = zv.y + dy; o.z = zv.z + dz; o.w = zv.w + dw;
        outq[e] = o;
        lsum += (double)(dx * dx) + (double)(dy * dy)
              + (double)(dz * dz) + (double)(dw * dw);
    }
    __shared__ double s[8];
    #pragma unroll
    for (int o = 16; o; o >>= 1) lsum += __shfl_down_sync(0xFFFFFFFFu, lsum, o);
    if ((threadIdx.x & 31) == 0) s[threadIdx.x >> 5] = lsum;
    __syncthreads();
    if (threadIdx.x == 0) {
        double b = 0.0;
        #pragma unroll
        for (int i = 0; i < 8; i++) b += s[i];
        atomicAdd(&g_loss_acc, b);
    }
}

__global__ void k_final(float* __restrict__ out_loss, double inv_cnt) {
    *out_loss = (float)(0.25 * g_loss_acc * inv_cnt);
}

// ---------------------------------------------------------------------------
extern "C" void kernel_launch(void* const* d_in, const int* in_sizes, int n_in,
                              void* d_out, int out_size) {
    const float* z   = (const float*)d_in[0];
    const float* emb = (const float*)d_in[1];
    const int N = in_sizes[0] / DDIM;
    const int K = in_sizes[1] / DDIM;

    float* out      = (float*)d_out;
    float* out_q    = out;
    float* out_idx  = out + (size_t)N * DDIM;
    float* out_loss = out_idx + N;

    k_norms<<<N + K, 256>>>(z, emb, N);

    const size_t smem = (size_t)(DDIM * TM + DDIM * TN) * sizeof(float);
    cudaFuncSetAttribute(k_gemm, cudaFuncAttributeMaxDynamicSharedMemorySize,
                         (int)smem);
    k_gemm<<<N / TM, 256, smem>>>((const float4*)z, (const float4*)emb, K);

    k_select<<<N / 8, 256>>>(z, emb, out_idx, K);
    k_fallback<<<512, 256>>>(z, emb, out_idx, K);

    k_gather<<<1024, 256>>>((const float4*)z, (const float4*)emb,
                            (float4*)out_q, N * (DDIM / 4));

    k_final<<<1, 1>>>(out_loss, 1.0 / ((double)N * (double)DDIM));
}

// round 7
// speedup vs baseline: 52.0995x; 1.8480x over previous
#include <cuda_runtime.h>
#include <cuda_bf16.h>
#include <cfloat>
#include <math.h>
#include <cstdint>

#define DDIM 256
#define MAXK 2048
#define MAXN (1 << 17)
#define CAND_CAP 32

__device__ float  g_cn[MAXK];
__device__ float  g_zn[MAXN];
__device__ int    g_idx[MAXN];
__device__ int    g_flag_cnt;
__device__ int    g_flagged[MAXN];
__device__ double g_loss_acc;
__device__ float4 g_S[(size_t)MAXN * 256];    // approx scores, row stride 1024 f
__device__ __align__(16) __nv_bfloat16 g_ehi[MAXK * DDIM];
__device__ __align__(16) __nv_bfloat16 g_elo[MAXK * DDIM];

// ---------------- key packing ----------------
__device__ __forceinline__ unsigned long long packkey(float s, int idx) {
    unsigned u = __float_as_uint(s);
    u = (u & 0x80000000u) ? ~u : (u | 0x80000000u);
    return ((unsigned long long)u << 32) | (unsigned)idx;
}
__device__ __forceinline__ float unpackval(unsigned long long k) {
    unsigned u = (unsigned)(k >> 32);
    u = (u & 0x80000000u) ? (u ^ 0x80000000u) : ~u;
    return __uint_as_float(u);
}

// ---------------- mma helpers (baseline PTX; compiles for compute_103) -----
__device__ __forceinline__ uint32_t smem_u32(const void* p) {
    uint32_t a;
    asm("{ .reg .u64 t; cvta.to.shared.u64 t, %1; cvt.u32.u64 %0, t; }"
        : "=r"(a) : "l"(p));
    return a;
}
__device__ __forceinline__ void ldsm_x4(uint32_t* r, uint32_t addr) {
    asm volatile("ldmatrix.sync.aligned.m8n8.x4.shared.b16 {%0,%1,%2,%3}, [%4];"
                 : "=r"(r[0]), "=r"(r[1]), "=r"(r[2]), "=r"(r[3]) : "r"(addr));
}
__device__ __forceinline__ void ldsm_x2(uint32_t* r, uint32_t addr) {
    asm volatile("ldmatrix.sync.aligned.m8n8.x2.shared.b16 {%0,%1}, [%2];"
                 : "=r"(r[0]), "=r"(r[1]) : "r"(addr));
}
__device__ __forceinline__ void mma16816(float* c, const uint32_t* a,
                                         const uint32_t* b) {
    asm volatile(
        "mma.sync.aligned.m16n8k16.row.col.f32.bf16.bf16.f32 "
        "{%0,%1,%2,%3}, {%4,%5,%6,%7}, {%8,%9}, {%0,%1,%2,%3};"
        : "+f"(c[0]), "+f"(c[1]), "+f"(c[2]), "+f"(c[3])
        : "r"(a[0]), "r"(a[1]), "r"(a[2]), "r"(a[3]), "r"(b[0]), "r"(b[1]));
}
// 16B-chunk swizzle: XOR low 3 chunk bits with row (works for 16/32-chunk rows)
__device__ __forceinline__ int chunk_sw(int c, int r) {
    return (c & ~7) | ((c ^ r) & 7);
}

// SMEM layout (bytes)
// z tiles: 128 rows x 512B (full D=256)    -> 65536 each
// e tiles: 128 codes x 256B (half D=128)   -> 32768 each
#define SM_ZHI 0
#define SM_ZLO 65536
#define SM_EHI 131072
#define SM_ELO 163840
#define SM_TOTAL 196608

// ---------------------------------------------------------------------------
// K1: fp64 norms -> fp32; reset accumulators.
// ---------------------------------------------------------------------------
__global__ void k_norms(const float* __restrict__ z,
                        const float* __restrict__ emb, int N) {
    const int b = blockIdx.x;
    const int t = threadIdx.x;
    const float* src = (b < N) ? (z + (size_t)b * DDIM)
                               : (emb + (size_t)(b - N) * DDIM);
    const float x = src[t];
    double v = (double)x * (double)x;
    __shared__ double s[8];
    #pragma unroll
    for (int o = 16; o; o >>= 1) v += __shfl_down_sync(0xFFFFFFFFu, v, o);
    if ((t & 31) == 0) s[t >> 5] = v;
    __syncthreads();
    if (t == 0) {
        double sum = 0.0;
        #pragma unroll
        for (int i = 0; i < 8; i++) sum += s[i];
        if (b < N) g_zn[b] = (float)sum; else g_cn[b - N] = (float)sum;
        if (b == 0) { g_loss_acc = 0.0; g_flag_cnt = 0; }
    }
}

// ---------------------------------------------------------------------------
// K1b: split codebook into bf16 hi/lo
// ---------------------------------------------------------------------------
__global__ void k_econv(const float* __restrict__ emb) {
    const int i = blockIdx.x * 256 + threadIdx.x;
    const float x = emb[i];
    const __nv_bfloat16 hi = __float2bfloat16(x);
    const __nv_bfloat16 lo = __float2bfloat16(x - __bfloat162float(hi));
    g_ehi[i] = hi;
    g_elo[i] = lo;
}

// ---------------------------------------------------------------------------
// K2: bf16 split GEMM via mma.sync m16n8k16 -> quantized scores in g_S.
// CTA: 128 rows. Per 128-code chunk: 2 half-D e-slices (dims 0-127, 128-255)
// staged in SMEM; fp32 accumulators carry across slices.
// 8 warps = 2(m) x 4(n), warp tile 64x32. Terms: zhi*ehi + zhi*elo + zlo*ehi.
// ---------------------------------------------------------------------------
__global__ void __launch_bounds__(256, 1)
k_gemm(const float4* __restrict__ z, int K) {
    extern __shared__ char smem[];
    const uint32_t sb = smem_u32(smem);
    const int tid = threadIdx.x;
    const int wid = tid >> 5;
    const int lane = tid & 31;
    const int row0 = blockIdx.x * 128;
    const int warp_m = wid >> 2;           // 0..1
    const int warp_n = wid & 3;            // 0..3
    float* Sf = (float*)g_S;

    // ---- fill z tiles: fp32 -> bf16 hi/lo, swizzled 16B chunks (32/row) ----
    for (int i = tid; i < 128 * 32; i += 256) {
        const int r = i >> 5;               // row in tile
        const int c = i & 31;               // 16B chunk (8 bf16 = 8 dims)
        const float4 v0 = z[(size_t)(row0 + r) * 64 + c * 2];
        const float4 v1 = z[(size_t)(row0 + r) * 64 + c * 2 + 1];
        const float xs[8] = {v0.x, v0.y, v0.z, v0.w, v1.x, v1.y, v1.z, v1.w};
        uint32_t hw[4], lw[4];
        #pragma unroll
        for (int q = 0; q < 4; q++) {
            const __nv_bfloat16 h0 = __float2bfloat16(xs[2 * q]);
            const __nv_bfloat16 h1 = __float2bfloat16(xs[2 * q + 1]);
            const __nv_bfloat16 l0 =
                __float2bfloat16(xs[2 * q] - __bfloat162float(h0));
            const __nv_bfloat16 l1 =
                __float2bfloat16(xs[2 * q + 1] - __bfloat162float(h1));
            hw[q] = (uint32_t)__bfloat16_as_ushort(h0)
                  | ((uint32_t)__bfloat16_as_ushort(h1) << 16);
            lw[q] = (uint32_t)__bfloat16_as_ushort(l0)
                  | ((uint32_t)__bfloat16_as_ushort(l1) << 16);
        }
        const int off = r * 512 + chunk_sw(c, r) * 16;
        *(uint4*)(smem + SM_ZHI + off) = make_uint4(hw[0], hw[1], hw[2], hw[3]);
        *(uint4*)(smem + SM_ZLO + off) = make_uint4(lw[0], lw[1], lw[2], lw[3]);
    }

    const int nchunk = K / 128;
    for (int kc = 0; kc < nchunk; kc++) {
        const int k0 = kc * 128;

        float acc[4][4][4];
        #pragma unroll
        for (int mt = 0; mt < 4; mt++)
            #pragma unroll
            for (int nt = 0; nt < 4; nt++)
                #pragma unroll
                for (int q = 0; q < 4; q++) acc[mt][nt][q] = 0.f;

        #pragma unroll 1
        for (int dh = 0; dh < 2; dh++) {
            __syncthreads();                // prev compute done reading e tiles
            // ---- fill e half-D slice: 128 codes x 128 dims (16 chunks/row) --
            const uint4* shi = (const uint4*)(g_ehi + (size_t)k0 * DDIM);
            const uint4* slo = (const uint4*)(g_elo + (size_t)k0 * DDIM);
            for (int i = tid; i < 128 * 16; i += 256) {
                const int r = i >> 4;
                const int c = i & 15;
                const int off = r * 256 + chunk_sw(c, r) * 16;
                *(uint4*)(smem + SM_EHI + off) = shi[r * 32 + dh * 16 + c];
                *(uint4*)(smem + SM_ELO + off) = slo[r * 32 + dh * 16 + c];
            }
            __syncthreads();

            #pragma unroll 1
            for (int ks = 0; ks < 8; ks++) {
                uint32_t ahi[4][4], alo[4][4], bhi[4][2], blo[4][2];
                // A frags: 16 rows (lane&15), k-half = lane>>4
                #pragma unroll
                for (int mt = 0; mt < 4; mt++) {
                    const int r = warp_m * 64 + mt * 16 + (lane & 15);
                    const int c = dh * 16 + ks * 2 + (lane >> 4);
                    const uint32_t off =
                        (uint32_t)(r * 512 + chunk_sw(c, r) * 16);
                    ldsm_x4(ahi[mt], sb + SM_ZHI + off);
                    ldsm_x4(alo[mt], sb + SM_ZLO + off);
                }
                // B frags: 8 codes (lane&7), k-half = (lane>>3)&1
                #pragma unroll
                for (int nt = 0; nt < 4; nt++) {
                    const int n = warp_n * 32 + nt * 8 + (lane & 7);
                    const int c = ks * 2 + ((lane >> 3) & 1);
                    const uint32_t off =
                        (uint32_t)(n * 256 + chunk_sw(c, n) * 16);
                    ldsm_x2(bhi[nt], sb + SM_EHI + off);
                    ldsm_x2(blo[nt], sb + SM_ELO + off);
                }
                #pragma unroll
                for (int mt = 0; mt < 4; mt++)
                    #pragma unroll
                    for (int nt = 0; nt < 4; nt++) {
                        mma16816(acc[mt][nt], ahi[mt], bhi[nt]);
                        mma16816(acc[mt][nt], ahi[mt], blo[nt]);
                        mma16816(acc[mt][nt], alo[mt], bhi[nt]);
                    }
            }
        }

        // ---- epilogue: quantized scores -> g_S ----
        #pragma unroll
        for (int mt = 0; mt < 4; mt++) {
            const int rA = row0 + warp_m * 64 + mt * 16 + (lane >> 2);
            const int rB = rA + 8;
            const float znA = g_zn[rA], znB = g_zn[rB];
            #pragma unroll
            for (int nt = 0; nt < 4; nt++) {
                const int col = k0 + warp_n * 32 + nt * 8 + (lane & 3) * 2;
                const float cn0 = g_cn[col], cn1 = g_cn[col + 1];
                float2 sA, sB;
                sA.x = (znA + cn0) - 2.0f * acc[mt][nt][0];
                sA.y = (znA + cn1) - 2.0f * acc[mt][nt][1];
                sB.x = (znB + cn0) - 2.0f * acc[mt][nt][2];
                sB.y = (znB + cn1) - 2.0f * acc[mt][nt][3];
                *(float2*)(Sf + (size_t)rA * 1024 + col) = sA;
                *(float2*)(Sf + (size_t)rB * 1024 + col) = sB;
            }
        }
    }
}

// ---------------------------------------------------------------------------
// K3: per-row select: approx min -> provable band -> exact fp64 rescore.
// ---------------------------------------------------------------------------
__global__ void __launch_bounds__(256)
k_select(const float* __restrict__ z, const float* __restrict__ emb,
         float* __restrict__ out_idx_f, int K) {
    __shared__ int scnt[8];
    __shared__ int scand[8][CAND_CAP];

    const int warp = threadIdx.x >> 5;
    const int lane = threadIdx.x & 31;
    const int row  = blockIdx.x * 8 + warp;
    const float4* srow = g_S + (size_t)row * 256;
    const int E = K / 4;

    if (lane == 0) scnt[warp] = 0;
    __syncwarp();

    unsigned long long bk = ~0ull;
    for (int e = lane; e < E; e += 32) {
        const float4 v = srow[e];
        const int k = e * 4;
        unsigned long long k0 = packkey(v.x, k);
        unsigned long long k1 = packkey(v.y, k + 1);
        unsigned long long k2 = packkey(v.z, k + 2);
        unsigned long long k3 = packkey(v.w, k + 3);
        k0 = min(k0, k1); k2 = min(k2, k3); k0 = min(k0, k2);
        bk = min(bk, k0);
    }
    #pragma unroll
    for (int o = 16; o; o >>= 1)
        bk = min(bk, __shfl_xor_sync(0xFFFFFFFFu, bk, o));

    const float smin = unpackval(bk);
    const float aq = fabsf(smin);
    float qq = (aq > 0.f) ? exp2f((float)(ilogbf(aq) - 22)) : 1e-30f;  // 2*ulp
    const float thr = smin + (2.0f * qq + 6e-5f);

    for (int e = lane; e < E; e += 32) {
        const float4 v = srow[e];
        const float sv[4] = {v.x, v.y, v.z, v.w};
        #pragma unroll
        for (int q = 0; q < 4; q++) {
            if (sv[q] <= thr) {
                const int pos = atomicAdd(&scnt[warp], 1);
                if (pos < CAND_CAP) scand[warp][pos] = e * 4 + q;
            }
        }
    }
    __syncwarp();
    const int cnt = scnt[warp];

    if (cnt > CAND_CAP) {
        if (lane == 0) {
            const int p = atomicAdd(&g_flag_cnt, 1);
            g_flagged[p] = row;
        }
        return;
    }

    float zreg[8];
    const float* zr = z + (size_t)row * DDIM;
    #pragma unroll
    for (int t = 0; t < 8; t++) zreg[t] = zr[lane + 32 * t];
    const float zn = g_zn[row];

    unsigned long long best = ~0ull;
    for (int c = 0; c < cnt; c += 2) {
        const int i1 = scand[warp][c];
        const int i2 = (c + 1 < cnt) ? scand[warp][c + 1] : i1;
        const float* e1 = emb + (size_t)i1 * DDIM;
        const float* e2 = emb + (size_t)i2 * DDIM;
        double d1 = 0.0, d2 = 0.0;
        #pragma unroll
        for (int t = 0; t < 8; t++) {
            const double zd = (double)zreg[t];
            d1 += zd * (double)__ldg(e1 + lane + 32 * t);
            d2 += zd * (double)__ldg(e2 + lane + 32 * t);
        }
        #pragma unroll
        for (int o = 16; o; o >>= 1) {
            d1 += __shfl_down_sync(0xFFFFFFFFu, d1, o);
            d2 += __shfl_down_sync(0xFFFFFFFFu, d2, o);
        }
        if (lane == 0) {
            const float s1 = (zn + g_cn[i1]) - 2.0f * (float)d1;
            best = min(best, packkey(s1, i1));
            if (i2 != i1) {
                const float s2 = (zn + g_cn[i2]) - 2.0f * (float)d2;
                best = min(best, packkey(s2, i2));
            }
        }
    }
    if (lane == 0) {
        const int win = (int)(unsigned)(best & 0xFFFFFFFFull);
        g_idx[row] = win;
        out_idx_f[row] = (float)win;
    }
}

// ---------------------------------------------------------------------------
// K4: full-K fp64 fallback for flagged rows (rare).
// ---------------------------------------------------------------------------
__global__ void k_fallback(const float* __restrict__ z,
                           const float* __restrict__ emb,
                           float* __restrict__ out_idx_f, int K) {
    __shared__ float zrow[DDIM];
    __shared__ unsigned long long best;
    const int cnt = g_flag_cnt;
    for (int f = blockIdx.x; f < cnt; f += gridDim.x) {
        const int row = g_flagged[f];
        if (threadIdx.x == 0) best = ~0ull;
        for (int t = threadIdx.x; t < DDIM; t += blockDim.x)
            zrow[t] = z[(size_t)row * DDIM + t];
        __syncthreads();
        const float zn = g_zn[row];
        unsigned long long lb = ~0ull;
        for (int k = threadIdx.x; k < K; k += blockDim.x) {
            double dot = 0.0;
            const float* ek = emb + (size_t)k * DDIM;
            #pragma unroll 8
            for (int d = 0; d < DDIM; d++)
                dot += (double)zrow[d] * (double)ek[d];
            const float s = (zn + g_cn[k]) - 2.0f * (float)dot;
            lb = min(lb, packkey(s, k));
        }
        atomicMin(&best, lb);
        __syncthreads();
        if (threadIdx.x == 0) {
            const int win = (int)(unsigned)(best & 0xFFFFFFFFull);
            g_idx[row] = win;
            out_idx_f[row] = (float)win;
        }
        __syncthreads();
    }
}

// ---------------------------------------------------------------------------
// K5: gather + straight-through + fp64 loss
// ---------------------------------------------------------------------------
__global__ void k_gather(const float4* __restrict__ z,
                         const float4* __restrict__ emb,
                         float4* __restrict__ outq, int total4) {
    double lsum = 0.0;
    const int stride = gridDim.x * blockDim.x;
    for (int e = blockIdx.x * blockDim.x + threadIdx.x; e < total4; e += stride) {
        const int row = e >> 6;
        const int t   = e & 63;
        const int idx = g_idx[row];
        const float4 ev = emb[(size_t)idx * 64 + t];
        const float4 zv = z[e];
        const float dx = ev.x - zv.x, dy = ev.y - zv.y;
        const float dz = ev.z - zv.z, dw = ev.w - zv.w;
        float4 o;
        o.x = zv.x + dx; o.y = zv.y + dy; o.z = zv.z + dz; o.w = zv.w + dw;
        outq[e] = o;
        lsum += (double)(dx * dx) + (double)(dy * dy)
              + (double)(dz * dz) + (double)(dw * dw);
    }
    __shared__ double s[8];
    #pragma unroll
    for (int o = 16; o; o >>= 1) lsum += __shfl_down_sync(0xFFFFFFFFu, lsum, o);
    if ((threadIdx.x & 31) == 0) s[threadIdx.x >> 5] = lsum;
    __syncthreads();
    if (threadIdx.x == 0) {
        double b = 0.0;
        #pragma unroll
        for (int i = 0; i < 8; i++) b += s[i];
        atomicAdd(&g_loss_acc, b);
    }
}

__global__ void k_final(float* __restrict__ out_loss, double inv_cnt) {
    *out_loss = (float)(0.25 * g_loss_acc * inv_cnt);
}

// ---------------------------------------------------------------------------
extern "C" void kernel_launch(void* const* d_in, const int* in_sizes, int n_in,
                              void* d_out, int out_size) {
    const float* z   = (const float*)d_in[0];
    const float* emb = (const float*)d_in[1];
    const int N = in_sizes[0] / DDIM;
    const int K = in_sizes[1] / DDIM;

    float* out      = (float*)d_out;
    float* out_q    = out;
    float* out_idx  = out + (size_t)N * DDIM;
    float* out_loss = out_idx + N;

    k_norms<<<N + K, 256>>>(z, emb, N);
    k_econv<<<K, 256>>>(emb);

    cudaFuncSetAttribute(k_gemm, cudaFuncAttributeMaxDynamicSharedMemorySize,
                         SM_TOTAL);
    k_gemm<<<N / 128, 256, SM_TOTAL>>>((const float4*)z, K);

    k_select<<<N / 8, 256>>>(z, emb, out_idx, K);
    k_fallback<<<512, 256>>>(z, emb, out_idx, K);

    k_gather<<<1024, 256>>>((const float4*)z, (const float4*)emb,
                            (float4*)out_q, N * (DDIM / 4));

    k_final<<<1, 1>>>(out_loss, 1.0 / ((double)N * (double)DDIM));
}

// round 8
// speedup vs baseline: 53.5708x; 1.0282x over previous
#include <cuda_runtime.h>
#include <cuda_bf16.h>
#include <cfloat>
#include <math.h>
#include <cstdint>

#define DDIM 256
#define MAXK 2048
#define MAXN (1 << 17)
#define CAND_CAP 32

__device__ float  g_cn[MAXK];
__device__ float  g_zn[MAXN];
__device__ int    g_idx[MAXN];
__device__ int    g_flag_cnt;
__device__ int    g_flagged[MAXN];
__device__ double g_loss_acc;
__device__ float4 g_S[(size_t)MAXN * 256];    // approx scores, row stride 1024 f
__device__ unsigned long long g_rowmin[MAXN];
__device__ __align__(16) __nv_bfloat16 g_ehi[MAXK * DDIM];
__device__ __align__(16) __nv_bfloat16 g_elo[MAXK * DDIM];

// ---------------- key packing ----------------
__device__ __forceinline__ unsigned long long packkey(float s, int idx) {
    unsigned u = __float_as_uint(s);
    u = (u & 0x80000000u) ? ~u : (u | 0x80000000u);
    return ((unsigned long long)u << 32) | (unsigned)idx;
}
__device__ __forceinline__ float unpackval(unsigned long long k) {
    unsigned u = (unsigned)(k >> 32);
    u = (u & 0x80000000u) ? (u ^ 0x80000000u) : ~u;
    return __uint_as_float(u);
}

// ---------------- PTX helpers (baseline ISA; compiles for compute_103) -----
__device__ __forceinline__ uint32_t smem_u32(const void* p) {
    uint32_t a;
    asm("{ .reg .u64 t; cvta.to.shared.u64 t, %1; cvt.u32.u64 %0, t; }"
        : "=r"(a) : "l"(p));
    return a;
}
__device__ __forceinline__ void ldsm_x4(uint32_t* r, uint32_t addr) {
    asm volatile("ldmatrix.sync.aligned.m8n8.x4.shared.b16 {%0,%1,%2,%3}, [%4];"
                 : "=r"(r[0]), "=r"(r[1]), "=r"(r[2]), "=r"(r[3]) : "r"(addr));
}
__device__ __forceinline__ void ldsm_x2(uint32_t* r, uint32_t addr) {
    asm volatile("ldmatrix.sync.aligned.m8n8.x2.shared.b16 {%0,%1}, [%2];"
                 : "=r"(r[0]), "=r"(r[1]) : "r"(addr));
}
__device__ __forceinline__ void mma16816(float* c, const uint32_t* a,
                                         const uint32_t* b) {
    asm volatile(
        "mma.sync.aligned.m16n8k16.row.col.f32.bf16.bf16.f32 "
        "{%0,%1,%2,%3}, {%4,%5,%6,%7}, {%8,%9}, {%0,%1,%2,%3};"
        : "+f"(c[0]), "+f"(c[1]), "+f"(c[2]), "+f"(c[3])
        : "r"(a[0]), "r"(a[1]), "r"(a[2]), "r"(a[3]), "r"(b[0]), "r"(b[1]));
}
__device__ __forceinline__ void cp16(uint32_t saddr, const void* gaddr) {
    asm volatile("cp.async.ca.shared.global [%0], [%1], 16;"
                 :: "r"(saddr), "l"(gaddr) : "memory");
}
__device__ __forceinline__ void cp_commit() {
    asm volatile("cp.async.commit_group;" ::: "memory");
}
__device__ __forceinline__ void cp_wait1() {
    asm volatile("cp.async.wait_group 1;" ::: "memory");
}
__device__ __forceinline__ void cp_wait0() {
    asm volatile("cp.async.wait_group 0;" ::: "memory");
}
// 16B-chunk swizzle: XOR low 3 chunk bits with row
__device__ __forceinline__ int chunk_sw(int c, int r) {
    return (c & ~7) | ((c ^ r) & 7);
}

// SMEM layout (bytes)
// z tiles: 128 rows x 512B (full D)          -> 65536 each (hi, lo)
// e stage buffers: 2 x {hi 16KB, lo 16KB}    -> 65536 total
//   stage slice = 128 codes x 64 dims (128B/row = 8 chunks)
// keys: 128 x u64
#define SM_ZHI  0
#define SM_ZLO  65536
#define SM_E    131072
#define SM_KEYS 196608
#define SM_TOTAL (196608 + 1024)

// ---------------------------------------------------------------------------
// K1: fp64 norms -> fp32; reset accumulators.
// ---------------------------------------------------------------------------
__global__ void k_norms(const float* __restrict__ z,
                        const float* __restrict__ emb, int N) {
    const int b = blockIdx.x;
    const int t = threadIdx.x;
    const float* src = (b < N) ? (z + (size_t)b * DDIM)
                               : (emb + (size_t)(b - N) * DDIM);
    const float x = src[t];
    double v = (double)x * (double)x;
    __shared__ double s[8];
    #pragma unroll
    for (int o = 16; o; o >>= 1) v += __shfl_down_sync(0xFFFFFFFFu, v, o);
    if ((t & 31) == 0) s[t >> 5] = v;
    __syncthreads();
    if (t == 0) {
        double sum = 0.0;
        #pragma unroll
        for (int i = 0; i < 8; i++) sum += s[i];
        if (b < N) g_zn[b] = (float)sum; else g_cn[b - N] = (float)sum;
        if (b == 0) { g_loss_acc = 0.0; g_flag_cnt = 0; }
    }
}

// ---------------------------------------------------------------------------
// K1b: split codebook into bf16 hi/lo
// ---------------------------------------------------------------------------
__global__ void k_econv(const float* __restrict__ emb) {
    const int i = blockIdx.x * 256 + threadIdx.x;
    const float x = emb[i];
    const __nv_bfloat16 hi = __float2bfloat16(x);
    const __nv_bfloat16 lo = __float2bfloat16(x - __bfloat162float(hi));
    g_ehi[i] = hi;
    g_elo[i] = lo;
}

// ---------------------------------------------------------------------------
// K2: bf16 split GEMM (mma.sync m16n8k16), cp.async double-buffered e-slices,
//     fused per-row running-min. Scores -> g_S, row mins -> g_rowmin.
// CTA = 128 rows; stages = 8 chunks x 4 quarter-D slices.
// 8 warps = 2(m) x 4(n), warp tile 64x32. Terms: zhi*ehi + zhi*elo + zlo*ehi.
// ---------------------------------------------------------------------------
__global__ void __launch_bounds__(256, 1)
k_gemm(const float4* __restrict__ z, int K) {
    extern __shared__ char smem[];
    const uint32_t sb = smem_u32(smem);
    unsigned long long* keys = (unsigned long long*)(smem + SM_KEYS);
    const int tid = threadIdx.x;
    const int wid = tid >> 5;
    const int lane = tid & 31;
    const int row0 = blockIdx.x * 128;
    const int warp_m = wid >> 2;           // 0..1
    const int warp_n = wid & 3;            // 0..3
    float* Sf = (float*)g_S;

    if (tid < 128) keys[tid] = ~0ull;

    // ---- fill z tiles: fp32 -> bf16 hi/lo, swizzled 16B chunks (32/row) ----
    for (int i = tid; i < 128 * 32; i += 256) {
        const int r = i >> 5;
        const int c = i & 31;
        const float4 v0 = z[(size_t)(row0 + r) * 64 + c * 2];
        const float4 v1 = z[(size_t)(row0 + r) * 64 + c * 2 + 1];
        const float xs[8] = {v0.x, v0.y, v0.z, v0.w, v1.x, v1.y, v1.z, v1.w};
        uint32_t hw[4], lw[4];
        #pragma unroll
        for (int q = 0; q < 4; q++) {
            const __nv_bfloat16 h0 = __float2bfloat16(xs[2 * q]);
            const __nv_bfloat16 h1 = __float2bfloat16(xs[2 * q + 1]);
            const __nv_bfloat16 l0 =
                __float2bfloat16(xs[2 * q] - __bfloat162float(h0));
            const __nv_bfloat16 l1 =
                __float2bfloat16(xs[2 * q + 1] - __bfloat162float(h1));
            hw[q] = (uint32_t)__bfloat16_as_ushort(h0)
                  | ((uint32_t)__bfloat16_as_ushort(h1) << 16);
            lw[q] = (uint32_t)__bfloat16_as_ushort(l0)
                  | ((uint32_t)__bfloat16_as_ushort(l1) << 16);
        }
        const int off = r * 512 + chunk_sw(c, r) * 16;
        *(uint4*)(smem + SM_ZHI + off) = make_uint4(hw[0], hw[1], hw[2], hw[3]);
        *(uint4*)(smem + SM_ZLO + off) = make_uint4(lw[0], lw[1], lw[2], lw[3]);
    }

    const int nchunk = K / 128;
    const int nstage = nchunk * 4;

    // prefetch lambda: stage s -> buffer s&1 (hi at +0, lo at +16384)
    auto prefetch = [&](int s) {
        const int kc = s >> 2, qd = s & 3;
        const uint4* shi = (const uint4*)(g_ehi + (size_t)kc * 128 * DDIM);
        const uint4* slo = (const uint4*)(g_elo + (size_t)kc * 128 * DDIM);
        const uint32_t dst = sb + SM_E + (uint32_t)(s & 1) * 32768;
        #pragma unroll
        for (int i = tid; i < 128 * 8; i += 256) {
            const int r = i >> 3;
            const int c = i & 7;
            const uint32_t off = (uint32_t)(r * 128 + ((c ^ r) & 7) * 16);
            cp16(dst + off,         &shi[r * 32 + qd * 8 + c]);
            cp16(dst + 16384 + off, &slo[r * 32 + qd * 8 + c]);
        }
    };

    prefetch(0);
    cp_commit();

    for (int kc = 0; kc < nchunk; kc++) {
        const int k0 = kc * 128;

        float acc[4][4][4];
        #pragma unroll
        for (int mt = 0; mt < 4; mt++)
            #pragma unroll
            for (int nt = 0; nt < 4; nt++)
                #pragma unroll
                for (int q = 0; q < 4; q++) acc[mt][nt][q] = 0.f;

        #pragma unroll 1
        for (int qd = 0; qd < 4; qd++) {
            const int s = kc * 4 + qd;
            if (s + 1 < nstage) { prefetch(s + 1); cp_commit(); cp_wait1(); }
            else                { cp_wait0(); }
            __syncthreads();

            const uint32_t ebase = sb + SM_E + (uint32_t)(s & 1) * 32768;
            #pragma unroll
            for (int ks = 0; ks < 4; ks++) {
                uint32_t ahi[4][4], alo[4][4], bhi[4][2], blo[4][2];
                // A frags: 16 rows (lane&15), k-half = lane>>4
                #pragma unroll
                for (int mt = 0; mt < 4; mt++) {
                    const int r = warp_m * 64 + mt * 16 + (lane & 15);
                    const int c = qd * 8 + ks * 2 + (lane >> 4);
                    const uint32_t off =
                        (uint32_t)(r * 512 + chunk_sw(c, r) * 16);
                    ldsm_x4(ahi[mt], sb + SM_ZHI + off);
                    ldsm_x4(alo[mt], sb + SM_ZLO + off);
                }
                // B frags: 8 codes (lane&7), k-half = (lane>>3)&1
                #pragma unroll
                for (int nt = 0; nt < 4; nt++) {
                    const int n = warp_n * 32 + nt * 8 + (lane & 7);
                    const int c = ks * 2 + ((lane >> 3) & 1);
                    const uint32_t off =
                        (uint32_t)(n * 128 + ((c ^ n) & 7) * 16);
                    ldsm_x2(bhi[nt], ebase + off);
                    ldsm_x2(blo[nt], ebase + 16384 + off);
                }
                #pragma unroll
                for (int mt = 0; mt < 4; mt++)
                    #pragma unroll
                    for (int nt = 0; nt < 4; nt++) {
                        mma16816(acc[mt][nt], ahi[mt], bhi[nt]);
                        mma16816(acc[mt][nt], ahi[mt], blo[nt]);
                        mma16816(acc[mt][nt], alo[mt], bhi[nt]);
                    }
            }
            __syncthreads();   // all warps done reading buf (s&1) before refill
        }

        // ---- epilogue: quantized scores -> g_S; fused row-min -> keys ----
        #pragma unroll
        for (int mt = 0; mt < 4; mt++) {
            const int rA = row0 + warp_m * 64 + mt * 16 + (lane >> 2);
            const int rB = rA + 8;
            const float znA = g_zn[rA], znB = g_zn[rB];
            unsigned long long mkA = ~0ull, mkB = ~0ull;
            #pragma unroll
            for (int nt = 0; nt < 4; nt++) {
                const int col = k0 + warp_n * 32 + nt * 8 + (lane & 3) * 2;
                const float cn0 = g_cn[col], cn1 = g_cn[col + 1];
                float2 sA, sB;
                sA.x = (znA + cn0) - 2.0f * acc[mt][nt][0];
                sA.y = (znA + cn1) - 2.0f * acc[mt][nt][1];
                sB.x = (znB + cn0) - 2.0f * acc[mt][nt][2];
                sB.y = (znB + cn1) - 2.0f * acc[mt][nt][3];
                *(float2*)(Sf + (size_t)rA * 1024 + col) = sA;
                *(float2*)(Sf + (size_t)rB * 1024 + col) = sB;
                mkA = min(mkA, min(packkey(sA.x, col), packkey(sA.y, col + 1)));
                mkB = min(mkB, min(packkey(sB.x, col), packkey(sB.y, col + 1)));
            }
            atomicMin(&keys[rA - row0], mkA);
            atomicMin(&keys[rB - row0], mkB);
        }
    }

    __syncthreads();
    if (tid < 128) g_rowmin[row0 + tid] = keys[tid];
}

// ---------------------------------------------------------------------------
// K3: per-row select: read fused min -> provable band -> single candidate
//     sweep -> exact fp64 rescore. Warp per row.
// ---------------------------------------------------------------------------
__global__ void __launch_bounds__(256)
k_select(const float* __restrict__ z, const float* __restrict__ emb,
         float* __restrict__ out_idx_f, int K) {
    __shared__ int scnt[8];
    __shared__ int scand[8][CAND_CAP];

    const int warp = threadIdx.x >> 5;
    const int lane = threadIdx.x & 31;
    const int row  = blockIdx.x * 8 + warp;
    const float4* srow = g_S + (size_t)row * 256;
    const int E = K / 4;

    if (lane == 0) scnt[warp] = 0;
    __syncwarp();

    const float smin = unpackval(g_rowmin[row]);
    const float aq = fabsf(smin);
    float qq = (aq > 0.f) ? exp2f((float)(ilogbf(aq) - 22)) : 1e-30f;  // 2*ulp
    const float thr = smin + (2.0f * qq + 6e-5f);

    for (int e = lane; e < E; e += 32) {
        const float4 v = srow[e];
        const float sv[4] = {v.x, v.y, v.z, v.w};
        #pragma unroll
        for (int q = 0; q < 4; q++) {
            if (sv[q] <= thr) {
                const int pos = atomicAdd(&scnt[warp], 1);
                if (pos < CAND_CAP) scand[warp][pos] = e * 4 + q;
            }
        }
    }
    __syncwarp();
    const int cnt = scnt[warp];

    if (cnt > CAND_CAP) {
        if (lane == 0) {
            const int p = atomicAdd(&g_flag_cnt, 1);
            g_flagged[p] = row;
        }
        return;
    }

    float zreg[8];
    const float* zr = z + (size_t)row * DDIM;
    #pragma unroll
    for (int t = 0; t < 8; t++) zreg[t] = zr[lane + 32 * t];
    const float zn = g_zn[row];

    unsigned long long best = ~0ull;
    for (int c = 0; c < cnt; c += 2) {
        const int i1 = scand[warp][c];
        const int i2 = (c + 1 < cnt) ? scand[warp][c + 1] : i1;
        const float* e1 = emb + (size_t)i1 * DDIM;
        const float* e2 = emb + (size_t)i2 * DDIM;
        double d1 = 0.0, d2 = 0.0;
        #pragma unroll
        for (int t = 0; t < 8; t++) {
            const double zd = (double)zreg[t];
            d1 += zd * (double)__ldg(e1 + lane + 32 * t);
            d2 += zd * (double)__ldg(e2 + lane + 32 * t);
        }
        #pragma unroll
        for (int o = 16; o; o >>= 1) {
            d1 += __shfl_down_sync(0xFFFFFFFFu, d1, o);
            d2 += __shfl_down_sync(0xFFFFFFFFu, d2, o);
        }
        if (lane == 0) {
            const float s1 = (zn + g_cn[i1]) - 2.0f * (float)d1;
            best = min(best, packkey(s1, i1));
            if (i2 != i1) {
                const float s2 = (zn + g_cn[i2]) - 2.0f * (float)d2;
                best = min(best, packkey(s2, i2));
            }
        }
    }
    if (lane == 0) {
        const int win = (int)(unsigned)(best & 0xFFFFFFFFull);
        g_idx[row] = win;
        out_idx_f[row] = (float)win;
    }
}

// ---------------------------------------------------------------------------
// K4: full-K fp64 fallback for flagged rows (rare).
// ---------------------------------------------------------------------------
__global__ void k_fallback(const float* __restrict__ z,
                           const float* __restrict__ emb,
                           float* __restrict__ out_idx_f, int K) {
    __shared__ float zrow[DDIM];
    __shared__ unsigned long long best;
    const int cnt = g_flag_cnt;
    for (int f = blockIdx.x; f < cnt; f += gridDim.x) {
        const int row = g_flagged[f];
        if (threadIdx.x == 0) best = ~0ull;
        for (int t = threadIdx.x; t < DDIM; t += blockDim.x)
            zrow[t] = z[(size_t)row * DDIM + t];
        __syncthreads();
        const float zn = g_zn[row];
        unsigned long long lb = ~0ull;
        for (int k = threadIdx.x; k < K; k += blockDim.x) {
            double dot = 0.0;
            const float* ek = emb + (size_t)k * DDIM;
            #pragma unroll 8
            for (int d = 0; d < DDIM; d++)
                dot += (double)zrow[d] * (double)ek[d];
            const float s = (zn + g_cn[k]) - 2.0f * (float)dot;
            lb = min(lb, packkey(s, k));
        }
        atomicMin(&best, lb);
        __syncthreads();
        if (threadIdx.x == 0) {
            const int win = (int)(unsigned)(best & 0xFFFFFFFFull);
            g_idx[row] = win;
            out_idx_f[row] = (float)win;
        }
        __syncthreads();
    }
}

// ---------------------------------------------------------------------------
// K5: gather + straight-through + fp64 loss
// ---------------------------------------------------------------------------
__global__ void k_gather(const float4* __restrict__ z,
                         const float4* __restrict__ emb,
                         float4* __restrict__ outq, int total4) {
    double lsum = 0.0;
    const int stride = gridDim.x * blockDim.x;
    for (int e = blockIdx.x * blockDim.x + threadIdx.x; e < total4; e += stride) {
        const int row = e >> 6;
        const int t   = e & 63;
        const int idx = g_idx[row];
        const float4 ev = emb[(size_t)idx * 64 + t];
        const float4 zv = z[e];
        const float dx = ev.x - zv.x, dy = ev.y - zv.y;
        const float dz = ev.z - zv.z, dw = ev.w - zv.w;
        float4 o;
        o.x = zv.x + dx; o.y = zv.y + dy; o.z = zv.z + dz; o.w = zv.w + dw;
        outq[e] = o;
        lsum += (double)(dx * dx) + (double)(dy * dy)
              + (double)(dz * dz) + (double)(dw * dw);
    }
    __shared__ double s[8];
    #pragma unroll
    for (int o = 16; o; o >>= 1) lsum += __shfl_down_sync(0xFFFFFFFFu, lsum, o);
    if ((threadIdx.x & 31) == 0) s[threadIdx.x >> 5] = lsum;
    __syncthreads();
    if (threadIdx.x == 0) {
        double b = 0.0;
        #pragma unroll
        for (int i = 0; i < 8; i++) b += s[i];
        atomicAdd(&g_loss_acc, b);
    }
}

__global__ void k_final(float* __restrict__ out_loss, double inv_cnt) {
    *out_loss = (float)(0.25 * g_loss_acc * inv_cnt);
}

// ---------------------------------------------------------------------------
extern "C" void kernel_launch(void* const* d_in, const int* in_sizes, int n_in,
                              void* d_out, int out_size) {
    const float* z   = (const float*)d_in[0];
    const float* emb = (const float*)d_in[1];
    const int N = in_sizes[0] / DDIM;
    const int K = in_sizes[1] / DDIM;

    float* out      = (float*)d_out;
    float* out_q    = out;
    float* out_idx  = out + (size_t)N * DDIM;
    float* out_loss = out_idx + N;

    k_norms<<<N + K, 256>>>(z, emb, N);
    k_econv<<<K, 256>>>(emb);

    cudaFuncSetAttribute(k_gemm, cudaFuncAttributeMaxDynamicSharedMemorySize,
                         SM_TOTAL);
    k_gemm<<<N / 128, 256, SM_TOTAL>>>((const float4*)z, K);

    k_select<<<N / 8, 256>>>(z, emb, out_idx, K);
    k_fallback<<<512, 256>>>(z, emb, out_idx, K);

    k_gather<<<1024, 256>>>((const float4*)z, (const float4*)emb,
                            (float4*)out_q, N * (DDIM / 4));

    k_final<<<1, 1>>>(out_loss, 1.0 / ((double)N * (double)DDIM));
}